// round 14
// baseline (speedup 1.0000x reference)
#include <cuda_runtime.h>

// Shapes (fixed):
//   x [64,512,32,32] fp32 (HW=1024 contiguous)
//   router_weights [512,16], router_bias [16]
//   bn_gamma/beta [512], ln_gamma/beta [512]
// Output fp32: new_x [64,512] | logits [64,16] | probs [64,16]

#define B_DIM 64
#define C_DIM 512
#define A_DIM 16
#define HW    1024
#define EPSF  1e-5f
#define NBLK   1024u   // single wave; 8 warps/block
#define NTILE  32768u  // B*C tiles of 1024 floats
#define NCHUNK 16384u  // 2 tiles per grab
#define NSURV  64u     // survivor blocks (one per batch row)

__device__ float    g_sum[B_DIM * C_DIM];   // per-(b,c) spatial sum
__device__ float    g_csum[2][C_DIM];       // per-channel sum   (parity buffered)
__device__ float    g_csq [2][C_DIM];       // per-channel sumsq (parity buffered)
__device__ unsigned g_tile[2] = {0u, 0u};   // work-stealing chunk counters (parity)
__device__ unsigned g_start = 0;            // start tickets (monotonic)
__device__ unsigned g_done  = 0;            // completion tickets (monotonic)

__global__ __launch_bounds__(256) void k_fused(
    const float* __restrict__ x,
    const float* __restrict__ rw,        // [512,16]
    const float* __restrict__ rbias,     // [16]
    const float* __restrict__ bng,
    const float* __restrict__ bnb,
    const float* __restrict__ lng,
    const float* __restrict__ lnb,
    float* __restrict__ out)
{
    __shared__ float nxl [C_DIM];        // new_x[b,c] * ln_gamma[c]
    __shared__ float part_pa[256], part_sw[256], part_sq[256];
    __shared__ float redG[8], redH[8];
    __shared__ float lsh[A_DIM];
    __shared__ float sG, sHb;
    __shared__ unsigned sstart, sdone;

    const int tid  = threadIdx.x;
    const int lane = tid & 31;
    const int wid  = tid >> 5;

    // ---------------- Launch parity (uniform: launches are serialized) ------
    if (tid == 0) sstart = atomicAdd(&g_start, 1u);
    __syncthreads();
    const unsigned par = (sstart / NBLK) & 1u;

    // ---------------- Phase 1: work-stealing spatial sums -------------------
    // Each warp grabs 2-tile chunks from g_tile[par]; the next ticket is
    // prefetched before processing so atomic latency hides under the loads.
    {
        const float4* gb = reinterpret_cast<const float4*>(x);
        unsigned v = 0xFFFFFFFFu;
        if (lane == 0) v = atomicAdd(&g_tile[par], 1u);
        v = __shfl_sync(0xFFFFFFFFu, v, 0);

#pragma unroll 1
        while (v < NCHUNK) {
            unsigned vn = 0xFFFFFFFFu;
            if (lane == 0) vn = atomicAdd(&g_tile[par], 1u);   // prefetch next

            const unsigned tileA = v * 2u;                     // == b*512 + c
            const unsigned tileB = tileA + 1u;
            const float4* pA = gb + (size_t)tileA * 256 + lane;
            const float4* pB = gb + (size_t)tileB * 256 + lane;

            float sA = 0.f, qA = 0.f, sB = 0.f, qB = 0.f;
#pragma unroll
            for (int k = 0; k < 8; ++k) {
                float4 a = pA[k * 32];
                sA += a.x + a.y + a.z + a.w;
                qA += a.x * a.x + a.y * a.y + a.z * a.z + a.w * a.w;
            }
#pragma unroll
            for (int k = 0; k < 8; ++k) {
                float4 b = pB[k * 32];
                sB += b.x + b.y + b.z + b.w;
                qB += b.x * b.x + b.y * b.y + b.z * b.z + b.w * b.w;
            }
#pragma unroll
            for (int o = 16; o; o >>= 1) {
                sA += __shfl_xor_sync(0xFFFFFFFFu, sA, o);
                qA += __shfl_xor_sync(0xFFFFFFFFu, qA, o);
                sB += __shfl_xor_sync(0xFFFFFFFFu, sB, o);
                qB += __shfl_xor_sync(0xFFFFFFFFu, qB, o);
            }
            if (lane == 0) {
                const unsigned cA = tileA & (C_DIM - 1u);
                const unsigned cB = tileB & (C_DIM - 1u);
                g_sum[tileA] = sA;
                g_sum[tileB] = sB;
                atomicAdd(&g_csum[par][cA], sA);       // RED (no return)
                atomicAdd(&g_csq [par][cA], qA);
                atomicAdd(&g_csum[par][cB], sB);
                atomicAdd(&g_csq [par][cB], qB);
            }
            v = __shfl_sync(0xFFFFFFFFu, vn, 0);
        }
    }

    // ---------------- Single ticket: wait for all phase-1 work --------------
    __threadfence();
    __syncthreads();
    if (tid == 0) sdone = atomicAdd(&g_done, 1u);
    __syncthreads();
    const unsigned old   = sdone;
    const unsigned idx   = old % NBLK;
    const unsigned dbase = old - idx;
    if (idx < NBLK - NSURV) return;                  // 960 blocks exit
    const int b = (int)(idx - (NBLK - NSURV));       // survivor -> batch row b

    if (tid == 0) {
        const unsigned target = dbase + NBLK;
        while ((int)(*(volatile unsigned*)&g_done - target) < 0) __nanosleep(32);
    }
    __syncthreads();
    __threadfence();                                  // acquire all phase-1 data

    // ---------------- Tail: stats + new_x row b + routing -------------------
    {
        const int c0 = tid, c1 = tid + 256;
        const float invM  = 1.0f / (float)(B_DIM * HW);
        const float invHW = 1.0f / (float)HW;

        float mu0 = g_csum[par][c0] * invM;
        float mu1 = g_csum[par][c1] * invM;
        float r0  = rsqrtf(g_csq[par][c0] * invM - mu0 * mu0 + EPSF);
        float r1  = rsqrtf(g_csq[par][c1] * invM - mu1 * mu1 + EPSF);

        float n0 = bng[c0] * (g_sum[b * C_DIM + c0] * invHW - mu0) * r0 + bnb[c0];
        float n1 = bng[c1] * (g_sum[b * C_DIM + c1] * invHW - mu1) * r1 + bnb[c1];
        out[b * C_DIM + c0] = n0;
        out[b * C_DIM + c1] = n1;

        float lg0 = lng[c0], lg1 = lng[c1];
        nxl[c0] = n0 * lg0;  nxl[c1] = n1 * lg1;

        // block-reduce G = sum nx*ln_gamma, H = sum nx*ln_beta
        float gp = n0 * lg0 + n1 * lg1;
        float hp = n0 * lnb[c0] + n1 * lnb[c1];
#pragma unroll
        for (int o = 16; o; o >>= 1) {
            gp += __shfl_xor_sync(0xFFFFFFFFu, gp, o);
            hp += __shfl_xor_sync(0xFFFFFFFFu, hp, o);
        }
        if (lane == 0) { redG[wid] = gp; redH[wid] = hp; }
    }

    // Reset the other parity's accumulators/counter for the next replay
    if (tid < 8) {
        g_csum[par ^ 1u][b * 8 + tid] = 0.f;
        g_csq [par ^ 1u][b * 8 + tid] = 0.f;
    }
    if (b == 0 && tid == 0) g_tile[par ^ 1u] = 0u;
    __syncthreads();
    if (tid == 0) {
        float g = 0.f, h = 0.f;
#pragma unroll
        for (int i = 0; i < 8; ++i) { g += redG[i]; h += redH[i]; }
        sG = g; sHb = h;
    }

    // Fused LN-weight + dot partials: thread (a = tid&15, grp = tid>>4)
    {
        const int a   = tid & 15;
        const int grp = tid >> 4;
        const float* wp  = rw  + (grp * 32) * A_DIM + a;
        const float* nlp = nxl + grp * 32;
        float pa = 0.f, sw = 0.f, sq = 0.f;
#pragma unroll
        for (int j = 0; j < 32; ++j) {
            float wv = wp[j * A_DIM];
            pa += nlp[j] * wv;
            sw += wv;
            sq += wv * wv;
        }
        part_pa[tid] = pa;  part_sw[tid] = sw;  part_sq[tid] = sq;
    }
    __syncthreads();

    // Logits + softmax
    float* logits_out = out + B_DIM * C_DIM;
    float* probs_out  = logits_out + B_DIM * A_DIM;

    if (tid < A_DIM) {
        float P = 0.f, SW = 0.f, SQ = 0.f;
#pragma unroll
        for (int g = 0; g < 16; ++g) {
            P  += part_pa[g * 16 + tid];
            SW += part_sw[g * 16 + tid];
            SQ += part_sq[g * 16 + tid];
        }
        const float invC = 1.0f / (float)C_DIM;
        float m    = SW * invC;
        float rstd = rsqrtf(SQ * invC - m * m + EPSF);
        float logit = rstd * (P - m * sG) + sHb + rbias[tid];
        lsh[tid] = logit;
        logits_out[b * A_DIM + tid] = logit;
    }
    __syncthreads();

    if (tid == 0) {
        float mx = lsh[0];
#pragma unroll
        for (int a = 1; a < A_DIM; ++a) mx = fmaxf(mx, lsh[a]);
        float e[A_DIM]; float ssum = 0.f;
#pragma unroll
        for (int a = 0; a < A_DIM; ++a) { e[a] = __expf(lsh[a] - mx); ssum += e[a]; }
        float inv = 1.0f / ssum;
#pragma unroll
        for (int a = 0; a < A_DIM; ++a) probs_out[b * A_DIM + a] = e[a] * inv;
    }
}

extern "C" void kernel_launch(void* const* d_in, const int* in_sizes, int n_in,
                              void* d_out, int out_size)
{
    const float* x        = (const float*)d_in[0];
    const float* rw       = (const float*)d_in[1];
    const float* rbias    = (const float*)d_in[2];
    const float* bn_gamma = (const float*)d_in[3];
    const float* bn_beta  = (const float*)d_in[4];
    const float* ln_gamma = (const float*)d_in[5];
    const float* ln_beta  = (const float*)d_in[6];

    k_fused<<<NBLK, 256>>>(x, rw, rbias, bn_gamma, bn_beta,
                           ln_gamma, ln_beta, (float*)d_out);
}

// round 15
// speedup vs baseline: 1.2938x; 1.2938x over previous
#include <cuda_runtime.h>

// Shapes (fixed):
//   x [64,512,32,32] fp32 (HW=1024 contiguous)
//   router_weights [512,16], router_bias [16]
//   bn_gamma/beta [512], ln_gamma/beta [512]
// Output fp32: new_x [64,512] | logits [64,16] | probs [64,16]

#define B_DIM 64
#define C_DIM 512
#define A_DIM 16
#define HW    1024
#define EPSF  1e-5f
#define NBLK  1024u    // single wave; 8 warps/block, 4 tiles/warp = 32768 tiles
#define NSURV 64u      // survivor blocks (one per batch row)

__device__ float    g_sum[B_DIM * C_DIM];   // per-(b,c) spatial sum
__device__ float    g_csum[2][C_DIM];       // per-channel sum   (parity buffered)
__device__ float    g_csq [2][C_DIM];       // per-channel sumsq (parity buffered)
__device__ unsigned g_start = 0;            // start tickets (monotonic)
__device__ unsigned g_done  = 0;            // completion tickets (monotonic)

__global__ __launch_bounds__(256) void k_fused(
    const float* __restrict__ x,
    const float* __restrict__ rw,        // [512,16]
    const float* __restrict__ rbias,     // [16]
    const float* __restrict__ bng,
    const float* __restrict__ bnb,
    const float* __restrict__ lng,
    const float* __restrict__ lnb,
    float* __restrict__ out)
{
    __shared__ float nxl [C_DIM];        // new_x[b,c] * ln_gamma[c]
    __shared__ float part_pa[256], part_sw[256], part_sq[256];
    __shared__ float redG[8], redH[8];
    __shared__ float lsh[A_DIM];
    __shared__ float sG, sHb;
    __shared__ unsigned sstart, sdone;

    const int tid  = threadIdx.x;
    const int lane = tid & 31;
    const int wid  = tid >> 5;

    // ---------------- Launch parity (uniform: launches are serialized) ------
    if (tid == 0) sstart = atomicAdd(&g_start, 1u);
    __syncthreads();
    const unsigned par = (sstart / NBLK) & 1u;

    // Zero the OTHER parity's accumulators for the next replay, up front.
    // Safe: par^1 was fully consumed by the previous (serialized) launch.
    if (blockIdx.x < 64u && tid < 8) {
        g_csum[par ^ 1u][blockIdx.x * 8u + tid] = 0.f;
        g_csq [par ^ 1u][blockIdx.x * 8u + tid] = 0.f;
    }

    // ---------------- Phase 1: spatial sums + fused channel atomics ---------
    // (round-10 layout: warp reduces 4 tiles, lane0 stores + RED channel adds)
    {
        unsigned tile0 = blockIdx.x * 32u + (unsigned)wid;
#pragma unroll 1
        for (unsigned i = 0; i < 4u; ++i) {
            unsigned tile = tile0 + i * 8u;              // == b*512 + c
            const float4* p = reinterpret_cast<const float4*>(x)
                            + (size_t)tile * 256;
            float s = 0.f, q = 0.f;
#pragma unroll
            for (int k = 0; k < 8; ++k) {
                float4 v = p[k * 32 + lane];
                s += v.x + v.y + v.z + v.w;
                q += v.x * v.x + v.y * v.y + v.z * v.z + v.w * v.w;
            }
#pragma unroll
            for (int o = 16; o; o >>= 1) {
                s += __shfl_xor_sync(0xFFFFFFFFu, s, o);
                q += __shfl_xor_sync(0xFFFFFFFFu, q, o);
            }
            if (lane == 0) {
                unsigned c = tile & (C_DIM - 1u);
                g_sum[tile] = s;
                atomicAdd(&g_csum[par][c], s);           // RED (no return)
                atomicAdd(&g_csq [par][c], q);
            }
        }
    }

    // ---------------- Single ticket: wait for all phase-1 work --------------
    __threadfence();
    __syncthreads();
    if (tid == 0) sdone = atomicAdd(&g_done, 1u);
    __syncthreads();
    const unsigned old   = sdone;
    const unsigned idx   = old % NBLK;
    const unsigned dbase = old - idx;
    if (idx < NBLK - NSURV) return;                  // 960 blocks exit
    const int b = (int)(idx - (NBLK - NSURV));       // survivor -> batch row b

    // ---- Pre-gate work (overlaps tid0's spin): weight-only partials --------
    // part_sw/part_sq depend ONLY on rw -> compute while waiting, hiding the
    // rw global-load latency. thread (a = tid&15, grp = tid>>4).
    {
        const int a   = tid & 15;
        const int grp = tid >> 4;
        const float* wp = rw + (grp * 32) * A_DIM + a;
        float sw = 0.f, sq = 0.f;
#pragma unroll
        for (int j = 0; j < 32; ++j) {
            float wv = wp[j * A_DIM];
            sw += wv;
            sq += wv * wv;
        }
        part_sw[tid] = sw;  part_sq[tid] = sq;
    }

    if (tid == 0) {
        const unsigned target = dbase + NBLK;
        while ((int)(*(volatile unsigned*)&g_done - target) < 0) __nanosleep(32);
    }
    __syncthreads();
    __threadfence();                                  // acquire all phase-1 data

    // ---------------- Tail: stats + new_x row b + routing -------------------
    {
        const int c0 = tid, c1 = tid + 256;
        const float invM  = 1.0f / (float)(B_DIM * HW);
        const float invHW = 1.0f / (float)HW;

        float mu0 = g_csum[par][c0] * invM;
        float mu1 = g_csum[par][c1] * invM;
        float r0  = rsqrtf(g_csq[par][c0] * invM - mu0 * mu0 + EPSF);
        float r1  = rsqrtf(g_csq[par][c1] * invM - mu1 * mu1 + EPSF);

        float n0 = bng[c0] * (g_sum[b * C_DIM + c0] * invHW - mu0) * r0 + bnb[c0];
        float n1 = bng[c1] * (g_sum[b * C_DIM + c1] * invHW - mu1) * r1 + bnb[c1];
        out[b * C_DIM + c0] = n0;
        out[b * C_DIM + c1] = n1;

        float lg0 = lng[c0], lg1 = lng[c1];
        nxl[c0] = n0 * lg0;  nxl[c1] = n1 * lg1;

        // block-reduce G = sum nx*ln_gamma, H = sum nx*ln_beta
        float gp = n0 * lg0 + n1 * lg1;
        float hp = n0 * lnb[c0] + n1 * lnb[c1];
#pragma unroll
        for (int o = 16; o; o >>= 1) {
            gp += __shfl_xor_sync(0xFFFFFFFFu, gp, o);
            hp += __shfl_xor_sync(0xFFFFFFFFu, hp, o);
        }
        if (lane == 0) { redG[wid] = gp; redH[wid] = hp; }
    }
    __syncthreads();
    if (tid == 0) {
        float g = 0.f, h = 0.f;
#pragma unroll
        for (int i = 0; i < 8; ++i) { g += redG[i]; h += redH[i]; }
        sG = g; sHb = h;
    }

    // Dot partials vs normalized row: thread (a = tid&15, grp = tid>>4).
    // rw is now L1/L2-hot from the pre-gate pass.
    {
        const int a   = tid & 15;
        const int grp = tid >> 4;
        const float* wp  = rw  + (grp * 32) * A_DIM + a;
        const float* nlp = nxl + grp * 32;
        float pa = 0.f;
#pragma unroll
        for (int j = 0; j < 32; ++j)
            pa += nlp[j] * wp[j * A_DIM];
        part_pa[tid] = pa;
    }
    __syncthreads();

    // Logits + softmax
    float* logits_out = out + B_DIM * C_DIM;
    float* probs_out  = logits_out + B_DIM * A_DIM;

    if (tid < A_DIM) {
        float P = 0.f, SW = 0.f, SQ = 0.f;
#pragma unroll
        for (int g = 0; g < 16; ++g) {
            P  += part_pa[g * 16 + tid];
            SW += part_sw[g * 16 + tid];
            SQ += part_sq[g * 16 + tid];
        }
        const float invC = 1.0f / (float)C_DIM;
        float m    = SW * invC;
        float rstd = rsqrtf(SQ * invC - m * m + EPSF);
        float logit = rstd * (P - m * sG) + sHb + rbias[tid];
        lsh[tid] = logit;
        logits_out[b * A_DIM + tid] = logit;
    }
    __syncthreads();

    if (tid == 0) {
        float mx = lsh[0];
#pragma unroll
        for (int a = 1; a < A_DIM; ++a) mx = fmaxf(mx, lsh[a]);
        float e[A_DIM]; float ssum = 0.f;
#pragma unroll
        for (int a = 0; a < A_DIM; ++a) { e[a] = __expf(lsh[a] - mx); ssum += e[a]; }
        float inv = 1.0f / ssum;
#pragma unroll
        for (int a = 0; a < A_DIM; ++a) probs_out[b * A_DIM + a] = e[a] * inv;
    }
}

extern "C" void kernel_launch(void* const* d_in, const int* in_sizes, int n_in,
                              void* d_out, int out_size)
{
    const float* x        = (const float*)d_in[0];
    const float* rw       = (const float*)d_in[1];
    const float* rbias    = (const float*)d_in[2];
    const float* bn_gamma = (const float*)d_in[3];
    const float* bn_beta  = (const float*)d_in[4];
    const float* ln_gamma = (const float*)d_in[5];
    const float* ln_beta  = (const float*)d_in[6];

    k_fused<<<NBLK, 256>>>(x, rw, rbias, bn_gamma, bn_beta,
                           ln_gamma, ln_beta, (float*)d_out);
}

// round 16
// speedup vs baseline: 1.3960x; 1.0790x over previous
#include <cuda_runtime.h>

// Shapes (fixed):
//   x [64,512,32,32] fp32 (HW=1024 contiguous)
//   router_weights [512,16], router_bias [16]
//   bn_gamma/beta [512], ln_gamma/beta [512]
// Output fp32: new_x [64,512] | logits [64,16] | probs [64,16]

#define B_DIM 64
#define C_DIM 512
#define A_DIM 16
#define HW    1024
#define EPSF  1e-5f
#define NBLK1 4096u    // K1: one warp per (b,c) tile, 8 warps/block
#define NBLK2 64u      // K2: one block per batch row

__device__ float    g_sum[B_DIM * C_DIM];   // per-(b,c) spatial sum
__device__ float    g_csum[2][C_DIM];       // per-channel sum   (parity buffered)
__device__ float    g_csq [2][C_DIM];       // per-channel sumsq (parity buffered)
__device__ unsigned g_sp = 0;               // K1 start tickets (monotonic)
__device__ unsigned g_st = 0;               // K2 start tickets (monotonic)

// ---------------------------------------------------------------------------
// K1: per-(b,c) spatial sum + sumsq (round-4 layout, proven 72% DRAM) with
// fused per-channel RED atomics. No tickets/fences — the kernel boundary is
// the global sync.
// ---------------------------------------------------------------------------
__global__ __launch_bounds__(256) void k_phase1(const float* __restrict__ x)
{
    __shared__ unsigned sstart;
    const int tid  = threadIdx.x;
    const int lane = tid & 31;

    if (tid == 0) sstart = atomicAdd(&g_sp, 1u);
    __syncthreads();
    const unsigned par = (sstart / NBLK1) & 1u;   // uniform per launch

    const unsigned tile = blockIdx.x * 8u + (unsigned)(tid >> 5);  // b*512 + c
    const float4* p = reinterpret_cast<const float4*>(x) + (size_t)tile * 256;

    float s = 0.f, q = 0.f;
#pragma unroll
    for (int k = 0; k < 8; ++k) {
        float4 v = p[k * 32 + lane];
        s += v.x + v.y + v.z + v.w;
        q += v.x * v.x + v.y * v.y + v.z * v.z + v.w * v.w;
    }
#pragma unroll
    for (int o = 16; o; o >>= 1) {
        s += __shfl_xor_sync(0xFFFFFFFFu, s, o);
        q += __shfl_xor_sync(0xFFFFFFFFu, q, o);
    }
    if (lane == 0) {
        const unsigned c = tile & (C_DIM - 1u);
        g_sum[tile] = s;
        atomicAdd(&g_csum[par][c], s);            // RED (no return)
        atomicAdd(&g_csq [par][c], q);
    }
}

// ---------------------------------------------------------------------------
// K2: stats + new_x row + algebraic-LN routing + softmax. One block per b.
// All inputs L2-hot (written by K1 / tiny params).
// ---------------------------------------------------------------------------
__global__ __launch_bounds__(256) void k_tail(
    const float* __restrict__ rw,        // [512,16]
    const float* __restrict__ rbias,     // [16]
    const float* __restrict__ bng,
    const float* __restrict__ bnb,
    const float* __restrict__ lng,
    const float* __restrict__ lnb,
    float* __restrict__ out)
{
    __shared__ float nxl [C_DIM];
    __shared__ float part_pa[256], part_sw[256], part_sq[256];
    __shared__ float redG[8], redH[8];
    __shared__ float lsh[A_DIM];
    __shared__ float sG, sHb;
    __shared__ unsigned sstart;

    const int tid  = threadIdx.x;
    const int lane = tid & 31;
    const int wid  = tid >> 5;
    const int b    = blockIdx.x;

    if (tid == 0) sstart = atomicAdd(&g_st, 1u);
    __syncthreads();
    const unsigned par = (sstart / NBLK2) & 1u;   // matches K1's parity

    // ---- stats + new_x row b + LN-gamma/beta dot terms ---------------------
    {
        const int c0 = tid, c1 = tid + 256;
        const float invM  = 1.0f / (float)(B_DIM * HW);
        const float invHW = 1.0f / (float)HW;

        float mu0 = g_csum[par][c0] * invM;
        float mu1 = g_csum[par][c1] * invM;
        float r0  = rsqrtf(g_csq[par][c0] * invM - mu0 * mu0 + EPSF);
        float r1  = rsqrtf(g_csq[par][c1] * invM - mu1 * mu1 + EPSF);

        float n0 = bng[c0] * (g_sum[b * C_DIM + c0] * invHW - mu0) * r0 + bnb[c0];
        float n1 = bng[c1] * (g_sum[b * C_DIM + c1] * invHW - mu1) * r1 + bnb[c1];
        out[b * C_DIM + c0] = n0;
        out[b * C_DIM + c1] = n1;

        float lg0 = lng[c0], lg1 = lng[c1];
        nxl[c0] = n0 * lg0;  nxl[c1] = n1 * lg1;

        float gp = n0 * lg0 + n1 * lg1;
        float hp = n0 * lnb[c0] + n1 * lnb[c1];
#pragma unroll
        for (int o = 16; o; o >>= 1) {
            gp += __shfl_xor_sync(0xFFFFFFFFu, gp, o);
            hp += __shfl_xor_sync(0xFFFFFFFFu, hp, o);
        }
        if (lane == 0) { redG[wid] = gp; redH[wid] = hp; }
    }

    // Zero the OTHER parity's slice for the replay after next (safe: its
    // consumers finished in the previous serialized launch).
    if (tid < 8) {
        g_csum[par ^ 1u][b * 8 + tid] = 0.f;
        g_csq [par ^ 1u][b * 8 + tid] = 0.f;
    }
    __syncthreads();
    if (tid == 0) {
        float g = 0.f, h = 0.f;
#pragma unroll
        for (int i = 0; i < 8; ++i) { g += redG[i]; h += redH[i]; }
        sG = g; sHb = h;
    }

    // Fused LN-weight + dot partials: thread (a = tid&15, grp = tid>>4)
    {
        const int a   = tid & 15;
        const int grp = tid >> 4;
        const float* wp  = rw  + (grp * 32) * A_DIM + a;
        const float* nlp = nxl + grp * 32;
        float pa = 0.f, sw = 0.f, sq = 0.f;
#pragma unroll
        for (int j = 0; j < 32; ++j) {
            float wv = wp[j * A_DIM];
            pa += nlp[j] * wv;
            sw += wv;
            sq += wv * wv;
        }
        part_pa[tid] = pa;  part_sw[tid] = sw;  part_sq[tid] = sq;
    }
    __syncthreads();

    // Logits + softmax
    float* logits_out = out + B_DIM * C_DIM;
    float* probs_out  = logits_out + B_DIM * A_DIM;

    if (tid < A_DIM) {
        float P = 0.f, SW = 0.f, SQ = 0.f;
#pragma unroll
        for (int g = 0; g < 16; ++g) {
            P  += part_pa[g * 16 + tid];
            SW += part_sw[g * 16 + tid];
            SQ += part_sq[g * 16 + tid];
        }
        const float invC = 1.0f / (float)C_DIM;
        float m    = SW * invC;
        float rstd = rsqrtf(SQ * invC - m * m + EPSF);
        float logit = rstd * (P - m * sG) + sHb + rbias[tid];
        lsh[tid] = logit;
        logits_out[b * A_DIM + tid] = logit;
    }
    __syncthreads();

    if (tid == 0) {
        float mx = lsh[0];
#pragma unroll
        for (int a = 1; a < A_DIM; ++a) mx = fmaxf(mx, lsh[a]);
        float e[A_DIM]; float ssum = 0.f;
#pragma unroll
        for (int a = 0; a < A_DIM; ++a) { e[a] = __expf(lsh[a] - mx); ssum += e[a]; }
        float inv = 1.0f / ssum;
#pragma unroll
        for (int a = 0; a < A_DIM; ++a) probs_out[b * A_DIM + a] = e[a] * inv;
    }
}

extern "C" void kernel_launch(void* const* d_in, const int* in_sizes, int n_in,
                              void* d_out, int out_size)
{
    const float* x        = (const float*)d_in[0];
    const float* rw       = (const float*)d_in[1];
    const float* rbias    = (const float*)d_in[2];
    const float* bn_gamma = (const float*)d_in[3];
    const float* bn_beta  = (const float*)d_in[4];
    const float* ln_gamma = (const float*)d_in[5];
    const float* ln_beta  = (const float*)d_in[6];

    k_phase1<<<NBLK1, 256>>>(x);
    k_tail  <<<NBLK2, 256>>>(rw, rbias, bn_gamma, bn_beta,
                             ln_gamma, ln_beta, (float*)d_out);
}